// round 1
// baseline (speedup 1.0000x reference)
#include <cuda_runtime.h>

#define BN_EPS 1e-3f

// Segment layout (static): degree-0..4
// starts: 0, 4096, 16384, 36864, 57344 ; sizes: 4096,12288,20480,20480,8192
static const int SEG_START[5] = {0, 4096, 16384, 36864, 57344};
static const int SEG_SIZE[5]  = {4096, 12288, 20480, 20480, 8192};
static const int REL_OFF[5]   = {0, 0, 12288, 32768, 53248};  // row offset within rel buffer (d>=1)

// -------- scratch (static device globals; no runtime allocation) --------
__device__ float    g_rel [61440 * 256];
__device__ float    g_bufA[65536 * 256];
__device__ float    g_bufB[65536 * 256];
__device__ float    g_h   [65536 * 512];
__device__ float    g_sum [1024 * 512];
__device__ unsigned g_maxu[1024 * 512];

// =======================================================================
// fp32 tiled GEMM core: 64x64 tile, BK=16, 256 threads, 4x4 per thread
// =======================================================================
#define TBM 64
#define TBN 64
#define TBK 16

__device__ __forceinline__ void gemm_acc(
    const float* __restrict__ A, int lda,
    const float* __restrict__ B, int ldb, int K,
    float acc[4][4], float As[TBK][TBM], float Bs[TBK][TBN])
{
    const int tid = threadIdx.x;
    const int tx  = tid & 15;
    const int ty  = tid >> 4;
    const int am  = tid >> 2;          // 0..63  (A row in tile)
    const int ak  = (tid & 3) * 4;     // 0,4,8,12
    const int bk  = tid >> 4;          // 0..15  (B row in tile)
    const int bn4 = (tid & 15) * 4;    // 0..60

    for (int kt = 0; kt < K; kt += TBK) {
#pragma unroll
        for (int i = 0; i < 4; i++) {
            int k = kt + ak + i;
            As[ak + i][am] = (k < K) ? A[(long)am * lda + k] : 0.f;
        }
        {
            int k = kt + bk;
            if (k < K) {
                float4 v = *reinterpret_cast<const float4*>(&B[(long)k * ldb + bn4]);
                Bs[bk][bn4 + 0] = v.x; Bs[bk][bn4 + 1] = v.y;
                Bs[bk][bn4 + 2] = v.z; Bs[bk][bn4 + 3] = v.w;
            } else {
                Bs[bk][bn4 + 0] = 0.f; Bs[bk][bn4 + 1] = 0.f;
                Bs[bk][bn4 + 2] = 0.f; Bs[bk][bn4 + 3] = 0.f;
            }
        }
        __syncthreads();
#pragma unroll
        for (int k = 0; k < TBK; k++) {
            float a0 = As[k][ty * 4 + 0], a1 = As[k][ty * 4 + 1];
            float a2 = As[k][ty * 4 + 2], a3 = As[k][ty * 4 + 3];
            float b0 = Bs[k][tx * 4 + 0], b1 = Bs[k][tx * 4 + 1];
            float b2 = Bs[k][tx * 4 + 2], b3 = Bs[k][tx * 4 + 3];
            acc[0][0] += a0 * b0; acc[0][1] += a0 * b1; acc[0][2] += a0 * b2; acc[0][3] += a0 * b3;
            acc[1][0] += a1 * b0; acc[1][1] += a1 * b1; acc[1][2] += a1 * b2; acc[1][3] += a1 * b3;
            acc[2][0] += a2 * b0; acc[2][1] += a2 * b1; acc[2][2] += a2 * b2; acc[2][3] += a2 * b3;
            acc[3][0] += a3 * b0; acc[3][1] += a3 * b1; acc[3][2] += a3 * b2; acc[3][3] += a3 * b3;
        }
        __syncthreads();
    }
}

// =======================================================================
// Graph-conv GEMM: per-64-row-block segment select, dual-A (self + rel),
// fused bias + ReLU + BN epilogue. N = 256 fixed.
// =======================================================================
__global__ void __launch_bounds__(256)
conv_gemm(const float* __restrict__ X, int K,
          const float* __restrict__ REL,
          const float* __restrict__ W,    // (9, K, 256)
          const float* __restrict__ bz,   // (9, 256)
          const float* __restrict__ bnp,  // (4, 256): g, b, m, v
          float* __restrict__ Y)          // (65536, 256)
{
    __shared__ float As[TBK][TBM];
    __shared__ float Bs[TBK][TBN];

    const int row0 = blockIdx.y * TBM;
    const int col0 = blockIdx.x * TBN;
    const int d = (row0 < 4096) ? 0 : (row0 < 16384) ? 1 : (row0 < 36864) ? 2
                : (row0 < 57344) ? 3 : 4;

    float acc[4][4] = {};
    const long wsz = (long)K * 256;
    const float* Ws = (d == 0) ? (W + 8 * wsz) : (W + (2 * d - 1) * wsz);
    gemm_acc(X + (long)row0 * K, K, Ws + col0, 256, K, acc, As, Bs);
    if (d > 0) {
        gemm_acc(REL + (long)(row0 - 4096) * K, K,
                 W + (2 * d - 2) * wsz + col0, 256, K, acc, As, Bs);
    }

    const int tx = threadIdx.x & 15;
    const int ty = threadIdx.x >> 4;
#pragma unroll
    for (int j = 0; j < 4; j++) {
        int c = col0 + tx * 4 + j;
        float bias = (d == 0) ? bz[8 * 256 + c]
                              : bz[(2 * d - 2) * 256 + c] + bz[(2 * d - 1) * 256 + c];
        float g  = bnp[c],       be = bnp[256 + c];
        float mu = bnp[512 + c], va = bnp[768 + c];
        float s  = g * rsqrtf(va + BN_EPS);
        float sh = be - mu * s;
#pragma unroll
        for (int i = 0; i < 4; i++) {
            float z = acc[i][j] + bias;
            z = fmaxf(z, 0.f);
            Y[(long)(row0 + ty * 4 + i) * 256 + c] = z * s + sh;
        }
    }
}

// =======================================================================
// Dense GEMM: Y = BN3(relu(X @ W + b)), X:(M,K) W:(K,N)
// =======================================================================
__global__ void __launch_bounds__(256)
dense_gemm(const float* __restrict__ X, int K,
           const float* __restrict__ W, int N,
           const float* __restrict__ bz,
           const float* __restrict__ bnp,  // (4, N)
           float* __restrict__ Y)
{
    __shared__ float As[TBK][TBM];
    __shared__ float Bs[TBK][TBN];

    const int row0 = blockIdx.y * TBM;
    const int col0 = blockIdx.x * TBN;
    float acc[4][4] = {};
    gemm_acc(X + (long)row0 * K, K, W + col0, N, K, acc, As, Bs);

    const int tx = threadIdx.x & 15;
    const int ty = threadIdx.x >> 4;
#pragma unroll
    for (int j = 0; j < 4; j++) {
        int c = col0 + tx * 4 + j;
        float bias = bz[c];
        float g  = bnp[c],         be = bnp[N + c];
        float mu = bnp[2 * N + c], va = bnp[3 * N + c];
        float s  = g * rsqrtf(va + BN_EPS);
        float sh = be - mu * s;
#pragma unroll
        for (int i = 0; i < 4; i++) {
            float z = acc[i][j] + bias;
            z = fmaxf(z, 0.f);
            Y[(long)(row0 + ty * 4 + i) * N + c] = z * s + sh;
        }
    }
}

// =======================================================================
// Gather-sum of neighbor rows: out[i,c] = sum_j X[adj[i,j], c]
// =======================================================================
__global__ void gather_sum(const float* __restrict__ X, int ldx,
                           const int* __restrict__ adj, int d, int nrows,
                           float* __restrict__ out)
{
    int idx = blockIdx.x * blockDim.x + threadIdx.x;
    int tot = nrows * ldx;
    if (idx >= tot) return;
    int i = idx / ldx;
    int c = idx - i * ldx;
    float s = 0.f;
    for (int j = 0; j < d; j++)
        s += X[(long)adj[i * d + j] * ldx + c];
    out[(long)i * ldx + c] = s;
}

// =======================================================================
// Pool: out[off+i, c] = max(X[off+i, c], max_j X[adj[i,j], c])  (C=256)
// =======================================================================
__global__ void pool_max(const float* __restrict__ X,
                         const int* __restrict__ adj, int d, int nrows, int off,
                         float* __restrict__ out)
{
    int idx = blockIdx.x * blockDim.x + threadIdx.x;
    int tot = nrows * 256;
    if (idx >= tot) return;
    int i = idx >> 8;
    int c = idx & 255;
    float m = X[(long)(off + i) * 256 + c];
    for (int j = 0; j < d; j++)
        m = fmaxf(m, X[(long)adj[i * d + j] * 256 + c]);
    out[(long)(off + i) * 256 + c] = m;
}

// =======================================================================
// Segment reduce (sum + max) via atomics; float max via monotonic uint
// =======================================================================
__device__ __forceinline__ unsigned ford(float f) {
    unsigned u = __float_as_uint(f);
    return u ^ (unsigned)(((int)u >> 31) | 0x80000000);
}
__device__ __forceinline__ float funord(unsigned v) {
    unsigned u = (v & 0x80000000u) ? (v ^ 0x80000000u) : ~v;
    return __uint_as_float(u);
}

__global__ void seg_init(float* __restrict__ ssum, unsigned* __restrict__ smax)
{
    int idx = blockIdx.x * blockDim.x + threadIdx.x;
    if (idx >= 1024 * 512) return;
    ssum[idx] = 0.f;
    smax[idx] = 0x007FFFFFu;  // ford(-inf)
}

__global__ void seg_reduce(const float* __restrict__ H,
                           const int* __restrict__ mem,
                           float* __restrict__ ssum, unsigned* __restrict__ smax)
{
    int idx = blockIdx.x * blockDim.x + threadIdx.x;
    if (idx >= 65536 * 512) return;
    int i = idx >> 9;
    int c = idx & 511;
    float v = H[idx];
    int m = mem[i];
    atomicAdd(&ssum[m * 512 + c], v);
    atomicMax(&smax[m * 512 + c], ford(v));
}

// fp = tanh([seg_sum | seg_max])  -> written directly into d_out fp region
__global__ void fp_tanh(const float* __restrict__ ssum,
                        const unsigned* __restrict__ smax,
                        float* __restrict__ fp)
{
    int idx = blockIdx.x * blockDim.x + threadIdx.x;
    if (idx >= 1024 * 1024) return;
    int b = idx >> 10;
    int c = idx & 1023;
    float v = (c < 512) ? ssum[b * 512 + c] : funord(smax[b * 512 + (c - 512)]);
    fp[idx] = tanhf(v);
}

// head: logits = fp @ W + b ; softmax over 2 classes
__global__ void head_kernel(const float* __restrict__ fp,
                            const float* __restrict__ W,   // (1024, 24)
                            const float* __restrict__ b,   // (24,)
                            float* __restrict__ soft,
                            float* __restrict__ logits)
{
    __shared__ float row[1024];
    __shared__ float lg[24];
    int bi = blockIdx.x;
    for (int c = threadIdx.x; c < 1024; c += blockDim.x)
        row[c] = fp[bi * 1024 + c];
    __syncthreads();
    if (threadIdx.x < 24) {
        int t = threadIdx.x;
        float acc = b[t];
        for (int k = 0; k < 1024; k++)
            acc += row[k] * W[k * 24 + t];
        lg[t] = acc;
        logits[bi * 24 + t] = acc;
    }
    __syncthreads();
    if (threadIdx.x < 12) {
        int t = threadIdx.x;
        float l0 = lg[2 * t], l1 = lg[2 * t + 1];
        float m  = fmaxf(l0, l1);
        float e0 = expf(l0 - m), e1 = expf(l1 - m);
        float inv = 1.f / (e0 + e1);
        soft[bi * 24 + 2 * t]     = e0 * inv;
        soft[bi * 24 + 2 * t + 1] = e1 * inv;
    }
}

// =======================================================================
// launch
// =======================================================================
extern "C" void kernel_launch(void* const* d_in, const int* in_sizes, int n_in,
                              void* d_out, int out_size)
{
    const float* atom       = (const float*)d_in[0];
    const int*   membership = (const int*)  d_in[2];
    const int*   adj[4]     = {(const int*)d_in[4], (const int*)d_in[5],
                               (const int*)d_in[6], (const int*)d_in[7]};
    const float* gc1W = (const float*)d_in[8];
    const float* gc1b = (const float*)d_in[9];
    const float* gc2W = (const float*)d_in[10];
    const float* gc2b = (const float*)d_in[11];
    const float* bn1  = (const float*)d_in[12];
    const float* bn2  = (const float*)d_in[13];
    const float* bn3  = (const float*)d_in[14];
    const float* dW   = (const float*)d_in[15];
    const float* db   = (const float*)d_in[16];
    const float* hW   = (const float*)d_in[17];
    const float* hb   = (const float*)d_in[18];

    float *rel, *bufA, *bufB, *h, *ssum;
    unsigned* smax;
    cudaGetSymbolAddress((void**)&rel,  g_rel);
    cudaGetSymbolAddress((void**)&bufA, g_bufA);
    cudaGetSymbolAddress((void**)&bufB, g_bufB);
    cudaGetSymbolAddress((void**)&h,    g_h);
    cudaGetSymbolAddress((void**)&ssum, g_sum);
    cudaGetSymbolAddress((void**)&smax, g_maxu);

    float* out        = (float*)d_out;
    float* out_soft   = out;                 // (1024, 12, 2)
    float* out_logits = out + 1024 * 24;     // (1024, 12, 2)
    float* out_fp     = out + 2 * 1024 * 24; // (1024, 1024)

    // ---------------- layer 1 (K = 75) ----------------
    for (int d = 1; d <= 4; d++) {
        int n = SEG_SIZE[d], tot = n * 75;
        gather_sum<<<(tot + 255) / 256, 256>>>(atom, 75, adj[d - 1], d, n,
                                               rel + (long)REL_OFF[d] * 75);
    }
    conv_gemm<<<dim3(4, 1024), 256>>>(atom, 75, rel, gc1W, gc1b, bn1, bufA);
    // pool 1: bufA -> bufB
    cudaMemcpyAsync(bufB, bufA, (size_t)4096 * 256 * sizeof(float),
                    cudaMemcpyDeviceToDevice);
    for (int d = 1; d <= 4; d++) {
        int n = SEG_SIZE[d], tot = n * 256;
        pool_max<<<(tot + 255) / 256, 256>>>(bufA, adj[d - 1], d, n, SEG_START[d], bufB);
    }

    // ---------------- layer 2 (K = 256) ----------------
    for (int d = 1; d <= 4; d++) {
        int n = SEG_SIZE[d], tot = n * 256;
        gather_sum<<<(tot + 255) / 256, 256>>>(bufB, 256, adj[d - 1], d, n,
                                               rel + (long)REL_OFF[d] * 256);
    }
    conv_gemm<<<dim3(4, 1024), 256>>>(bufB, 256, rel, gc2W, gc2b, bn2, bufA);
    cudaMemcpyAsync(bufB, bufA, (size_t)4096 * 256 * sizeof(float),
                    cudaMemcpyDeviceToDevice);
    for (int d = 1; d <= 4; d++) {
        int n = SEG_SIZE[d], tot = n * 256;
        pool_max<<<(tot + 255) / 256, 256>>>(bufA, adj[d - 1], d, n, SEG_START[d], bufB);
    }

    // ---------------- dense + BN3 ----------------
    dense_gemm<<<dim3(8, 1024), 256>>>(bufB, 256, dW, 512, db, bn3, h);

    // ---------------- segment sum/max ----------------
    seg_init<<<(1024 * 512 + 255) / 256, 256>>>(ssum, smax);
    seg_reduce<<<(65536 * 512 + 255) / 256, 256>>>(h, membership, ssum, smax);

    // ---------------- fp / head / softmax ----------------
    fp_tanh<<<(1024 * 1024 + 255) / 256, 256>>>(ssum, smax, out_fp);
    head_kernel<<<1024, 256>>>(out_fp, hW, hb, out_soft, out_logits);
}

// round 3
// speedup vs baseline: 1.9869x; 1.9869x over previous
#include <cuda_runtime.h>
#include <stdint.h>

#define BN_EPS 1e-3f
#define BK 32
#define AS_STRIDE 36
#define BS_STRIDE 136

// Segment layout (static): degree-0..4
static const int SEG_START[5] = {0, 4096, 16384, 36864, 57344};
static const int SEG_SIZE[5]  = {4096, 12288, 20480, 20480, 8192};
static const int REL_OFF[5]   = {0, 0, 12288, 32768, 53248};

// -------- scratch (static device globals; no runtime allocation) --------
__device__ float    g_rel [61440 * 256];
__device__ float    g_bufA[65536 * 256];
__device__ float    g_bufB[65536 * 256];
__device__ float    g_h   [65536 * 512];
__device__ float    g_sum [1024 * 512];
__device__ unsigned g_maxu[1024 * 512];

// ======================= MMA helpers =======================
__device__ __forceinline__ uint32_t f2tf(float f) {
    uint32_t r; asm("cvt.rna.tf32.f32 %0, %1;" : "=r"(r) : "f"(f)); return r;
}

__device__ __forceinline__ void mma8(float* d, const uint32_t* a, const uint32_t* b) {
    asm volatile("mma.sync.aligned.m16n8k8.row.col.f32.tf32.tf32.f32 "
        "{%0,%1,%2,%3}, {%4,%5,%6,%7}, {%8,%9}, {%0,%1,%2,%3};"
        : "+f"(d[0]), "+f"(d[1]), "+f"(d[2]), "+f"(d[3])
        : "r"(a[0]), "r"(a[1]), "r"(a[2]), "r"(a[3]), "r"(b[0]), "r"(b[1]));
}

// Load one BK-chunk of A (128 x 32, [m][k]) and B (32 x N-slice 128, [k][n]).
// A: row-major (rows x K). B = W: row-major (K x nstride), slice at col0.
__device__ __forceinline__ void load_tiles(
    uint32_t* As, uint32_t* Bs,
    const float* __restrict__ A, int K, int kt, bool avec,
    const float* __restrict__ W, int nstride, int col0, int tid)
{
    // A: thread -> row tid>>1, 16 cols at (tid&1)*16
    {
        const int ar = tid >> 1, ac0 = (tid & 1) * 16;
        const float* Ap = A + (long)ar * K + kt + ac0;
        uint32_t* Ad = As + ar * AS_STRIDE + ac0;
        if (avec) {
#pragma unroll
            for (int q = 0; q < 4; q++) {
                float4 v = *reinterpret_cast<const float4*>(Ap + q * 4);
                Ad[q * 4 + 0] = f2tf(v.x); Ad[q * 4 + 1] = f2tf(v.y);
                Ad[q * 4 + 2] = f2tf(v.z); Ad[q * 4 + 3] = f2tf(v.w);
            }
        } else {
#pragma unroll
            for (int i = 0; i < 16; i++) {
                int k = kt + ac0 + i;
                float v = (k < K) ? Ap[i] : 0.f;
                Ad[i] = f2tf(v);
            }
        }
    }
    // B: thread -> k-row tid>>3, 16 cols at (tid&7)*16
    {
        const int kr = tid >> 3, nb0 = (tid & 7) * 16;
        const int k = kt + kr;
        uint32_t* Bd = Bs + kr * BS_STRIDE + nb0;
        if (k < K) {
            const float* Bp = W + (long)k * nstride + col0 + nb0;
#pragma unroll
            for (int q = 0; q < 4; q++) {
                float4 v = *reinterpret_cast<const float4*>(Bp + q * 4);
                Bd[q * 4 + 0] = f2tf(v.x); Bd[q * 4 + 1] = f2tf(v.y);
                Bd[q * 4 + 2] = f2tf(v.z); Bd[q * 4 + 3] = f2tf(v.w);
            }
        } else {
#pragma unroll
            for (int i = 0; i < 16; i++) Bd[i] = 0u;
        }
    }
}

__device__ __forceinline__ void gemm_compute(
    const uint32_t* As, const uint32_t* Bs,
    float acc[16][4], int wm, int wn, int gid, int tig)
{
#pragma unroll
    for (int kk = 0; kk < 4; kk++) {
        const int kb = kk * 8;
        uint32_t a[4][4], b[4][2];
#pragma unroll
        for (int mt = 0; mt < 4; mt++) {
            int r = wm * 64 + mt * 16;
            a[mt][0] = As[(r + gid) * AS_STRIDE + kb + tig];
            a[mt][1] = As[(r + gid + 8) * AS_STRIDE + kb + tig];
            a[mt][2] = As[(r + gid) * AS_STRIDE + kb + tig + 4];
            a[mt][3] = As[(r + gid + 8) * AS_STRIDE + kb + tig + 4];
        }
#pragma unroll
        for (int nt = 0; nt < 4; nt++) {
            int c = wn * 32 + nt * 8;
            b[nt][0] = Bs[(kb + tig) * BS_STRIDE + c + gid];
            b[nt][1] = Bs[(kb + tig + 4) * BS_STRIDE + c + gid];
        }
#pragma unroll
        for (int mt = 0; mt < 4; mt++)
#pragma unroll
            for (int nt = 0; nt < 4; nt++)
                mma8(acc[mt * 4 + nt], a[mt], b[nt]);
    }
}

// ======================= conv GEMM (tf32 mma.sync) =======================
// Y[row0:+128, col0:+128] = BN(relu(X@Wself + [REL@Wrel] + bias)), N=256
__global__ void __launch_bounds__(256, 2)
conv_gemm_mma(const float* __restrict__ X, int K, int KCH,
              const float* __restrict__ REL,
              const float* __restrict__ W,    // (9, K, 256)
              const float* __restrict__ bz,   // (9, 256)
              const float* __restrict__ bnp,  // (4, 256)
              float* __restrict__ Y)          // (65536, 256)
{
    __shared__ uint32_t As[128 * AS_STRIDE];
    __shared__ uint32_t Bs[BK * BS_STRIDE];
    __shared__ float s_sc[128], s_sh[128], s_bi[128];

    const int tid = threadIdx.x;
    const int lane = tid & 31, wid = tid >> 5;
    const int gid = lane >> 2, tig = lane & 3;
    const int wm = wid & 1, wn = wid >> 1;
    const int row0 = blockIdx.y * 128;
    const int col0 = blockIdx.x * 128;
    const int d = (row0 < 4096) ? 0 : (row0 < 16384) ? 1 : (row0 < 36864) ? 2
                : (row0 < 57344) ? 3 : 4;

    if (tid < 128) {
        int c = col0 + tid;
        float bias = (d == 0) ? bz[8 * 256 + c]
                              : bz[(2 * d - 2) * 256 + c] + bz[(2 * d - 1) * 256 + c];
        float gg = bnp[c], be = bnp[256 + c], mu = bnp[512 + c], va = bnp[768 + c];
        float sc = gg * rsqrtf(va + BN_EPS);
        s_sc[tid] = sc; s_sh[tid] = be - mu * sc; s_bi[tid] = bias;
    }

    const long wsz = (long)K * 256;
    const float* A0 = X + (long)row0 * K;
    const float* W0 = W + ((d == 0) ? 8 : (2 * d - 1)) * wsz;
    const float* A1 = (d > 0) ? REL + (long)(row0 - 4096) * K : A0;
    const float* W1 = (d > 0) ? W + (2 * d - 2) * wsz : W0;
    const int npass = (d > 0) ? 2 : 1;
    const bool avec = ((K & 15) == 0);

    float acc[16][4];
#pragma unroll
    for (int i = 0; i < 16; i++)
        acc[i][0] = acc[i][1] = acc[i][2] = acc[i][3] = 0.f;

    for (int pass = 0; pass < npass; pass++) {
        const float* A = pass ? A1 : A0;
        const float* Wp = pass ? W1 : W0;
        for (int kc = 0; kc < KCH; kc++) {
            __syncthreads();
            load_tiles(As, Bs, A, K, kc * BK, avec, Wp, 256, col0, tid);
            __syncthreads();
            gemm_compute(As, Bs, acc, wm, wn, gid, tig);
        }
    }

#pragma unroll
    for (int mt = 0; mt < 4; mt++) {
#pragma unroll
        for (int nt = 0; nt < 4; nt++) {
            int cl = wn * 32 + nt * 8 + tig * 2;
            int r = row0 + wm * 64 + mt * 16 + gid;
            float* a4 = acc[mt * 4 + nt];
            float sc0 = s_sc[cl], sc1 = s_sc[cl + 1];
            float sh0 = s_sh[cl], sh1 = s_sh[cl + 1];
            float bi0 = s_bi[cl], bi1 = s_bi[cl + 1];
            float2 v;
            v.x = fmaxf(a4[0] + bi0, 0.f) * sc0 + sh0;
            v.y = fmaxf(a4[1] + bi1, 0.f) * sc1 + sh1;
            *reinterpret_cast<float2*>(&Y[(long)r * 256 + col0 + cl]) = v;
            v.x = fmaxf(a4[2] + bi0, 0.f) * sc0 + sh0;
            v.y = fmaxf(a4[3] + bi1, 0.f) * sc1 + sh1;
            *reinterpret_cast<float2*>(&Y[(long)(r + 8) * 256 + col0 + cl]) = v;
        }
    }
}

// ======================= dense GEMM (tf32 mma.sync) =======================
// H = BN3(relu(X @ Wd + b)); X:(65536,256), Wd:(256,512)
__global__ void __launch_bounds__(256, 2)
dense_gemm_mma(const float* __restrict__ X,
               const float* __restrict__ W,    // (256, 512)
               const float* __restrict__ bz,   // (512,)
               const float* __restrict__ bnp,  // (4, 512)
               float* __restrict__ Y)          // (65536, 512)
{
    __shared__ uint32_t As[128 * AS_STRIDE];
    __shared__ uint32_t Bs[BK * BS_STRIDE];
    __shared__ float s_sc[128], s_sh[128], s_bi[128];

    const int tid = threadIdx.x;
    const int lane = tid & 31, wid = tid >> 5;
    const int gid = lane >> 2, tig = lane & 3;
    const int wm = wid & 1, wn = wid >> 1;
    const int row0 = blockIdx.y * 128;
    const int col0 = blockIdx.x * 128;
    const int K = 256;

    if (tid < 128) {
        int c = col0 + tid;
        float gg = bnp[c], be = bnp[512 + c], mu = bnp[1024 + c], va = bnp[1536 + c];
        float sc = gg * rsqrtf(va + BN_EPS);
        s_sc[tid] = sc; s_sh[tid] = be - mu * sc; s_bi[tid] = bz[c];
    }

    float acc[16][4];
#pragma unroll
    for (int i = 0; i < 16; i++)
        acc[i][0] = acc[i][1] = acc[i][2] = acc[i][3] = 0.f;

    const float* A = X + (long)row0 * K;
    for (int kc = 0; kc < 8; kc++) {
        __syncthreads();
        load_tiles(As, Bs, A, K, kc * BK, true, W, 512, col0, tid);
        __syncthreads();
        gemm_compute(As, Bs, acc, wm, wn, gid, tig);
    }

#pragma unroll
    for (int mt = 0; mt < 4; mt++) {
#pragma unroll
        for (int nt = 0; nt < 4; nt++) {
            int cl = wn * 32 + nt * 8 + tig * 2;
            int r = row0 + wm * 64 + mt * 16 + gid;
            float* a4 = acc[mt * 4 + nt];
            float sc0 = s_sc[cl], sc1 = s_sc[cl + 1];
            float sh0 = s_sh[cl], sh1 = s_sh[cl + 1];
            float bi0 = s_bi[cl], bi1 = s_bi[cl + 1];
            float2 v;
            v.x = fmaxf(a4[0] + bi0, 0.f) * sc0 + sh0;
            v.y = fmaxf(a4[1] + bi1, 0.f) * sc1 + sh1;
            *reinterpret_cast<float2*>(&Y[(long)r * 512 + col0 + cl]) = v;
            v.x = fmaxf(a4[2] + bi0, 0.f) * sc0 + sh0;
            v.y = fmaxf(a4[3] + bi1, 0.f) * sc1 + sh1;
            *reinterpret_cast<float2*>(&Y[(long)(r + 8) * 512 + col0 + cl]) = v;
        }
    }
}

// ======================= gather / pool =======================
__global__ void gather_sum(const float* __restrict__ X, int ldx,
                           const int* __restrict__ adj, int d, int nrows,
                           float* __restrict__ out)
{
    int idx = blockIdx.x * blockDim.x + threadIdx.x;
    int tot = nrows * ldx;
    if (idx >= tot) return;
    int i = idx / ldx;
    int c = idx - i * ldx;
    float s = 0.f;
    for (int j = 0; j < d; j++)
        s += X[(long)adj[i * d + j] * ldx + c];
    out[(long)i * ldx + c] = s;
}

__global__ void pool_max(const float* __restrict__ X,
                         const int* __restrict__ adj, int d, int nrows, int off,
                         float* __restrict__ out)
{
    int idx = blockIdx.x * blockDim.x + threadIdx.x;
    int tot = nrows * 256;
    if (idx >= tot) return;
    int i = idx >> 8;
    int c = idx & 255;
    float m = X[(long)(off + i) * 256 + c];
    for (int j = 0; j < d; j++)
        m = fmaxf(m, X[(long)adj[i * d + j] * 256 + c]);
    out[(long)(off + i) * 256 + c] = m;
}

// ======================= segment reduce =======================
__device__ __forceinline__ unsigned ford(float f) {
    unsigned u = __float_as_uint(f);
    return u ^ (unsigned)(((int)u >> 31) | 0x80000000);
}
__device__ __forceinline__ float funord(unsigned v) {
    unsigned u = (v & 0x80000000u) ? (v ^ 0x80000000u) : ~v;
    return __uint_as_float(u);
}

__global__ void seg_init(float* __restrict__ ssum, unsigned* __restrict__ smax)
{
    int idx = blockIdx.x * blockDim.x + threadIdx.x;
    if (idx >= 1024 * 512) return;
    ssum[idx] = 0.f;
    smax[idx] = 0x007FFFFFu;
}

__global__ void seg_reduce(const float* __restrict__ H,
                           const int* __restrict__ mem,
                           float* __restrict__ ssum, unsigned* __restrict__ smax)
{
    int idx = blockIdx.x * blockDim.x + threadIdx.x;
    if (idx >= 65536 * 512) return;
    int i = idx >> 9;
    int c = idx & 511;
    float v = H[idx];
    int m = mem[i];
    atomicAdd(&ssum[m * 512 + c], v);
    atomicMax(&smax[m * 512 + c], ford(v));
}

__global__ void fp_tanh(const float* __restrict__ ssum,
                        const unsigned* __restrict__ smax,
                        float* __restrict__ fp)
{
    int idx = blockIdx.x * blockDim.x + threadIdx.x;
    if (idx >= 1024 * 1024) return;
    int b = idx >> 10;
    int c = idx & 1023;
    float v = (c < 512) ? ssum[b * 512 + c] : funord(smax[b * 512 + (c - 512)]);
    fp[idx] = tanhf(v);
}

__global__ void head_kernel(const float* __restrict__ fp,
                            const float* __restrict__ W,
                            const float* __restrict__ b,
                            float* __restrict__ soft,
                            float* __restrict__ logits)
{
    __shared__ float row[1024];
    __shared__ float lg[24];
    int bi = blockIdx.x;
    for (int c = threadIdx.x; c < 1024; c += blockDim.x)
        row[c] = fp[bi * 1024 + c];
    __syncthreads();
    if (threadIdx.x < 24) {
        int t = threadIdx.x;
        float acc = b[t];
        for (int k = 0; k < 1024; k++)
            acc += row[k] * W[k * 24 + t];
        lg[t] = acc;
        logits[bi * 24 + t] = acc;
    }
    __syncthreads();
    if (threadIdx.x < 12) {
        int t = threadIdx.x;
        float l0 = lg[2 * t], l1 = lg[2 * t + 1];
        float m  = fmaxf(l0, l1);
        float e0 = expf(l0 - m), e1 = expf(l1 - m);
        float inv = 1.f / (e0 + e1);
        soft[bi * 24 + 2 * t]     = e0 * inv;
        soft[bi * 24 + 2 * t + 1] = e1 * inv;
    }
}

// ======================= launch =======================
extern "C" void kernel_launch(void* const* d_in, const int* in_sizes, int n_in,
                              void* d_out, int out_size)
{
    const float* atom       = (const float*)d_in[0];
    const int*   membership = (const int*)  d_in[2];
    const int*   adj[4]     = {(const int*)d_in[4], (const int*)d_in[5],
                               (const int*)d_in[6], (const int*)d_in[7]};
    const float* gc1W = (const float*)d_in[8];
    const float* gc1b = (const float*)d_in[9];
    const float* gc2W = (const float*)d_in[10];
    const float* gc2b = (const float*)d_in[11];
    const float* bn1  = (const float*)d_in[12];
    const float* bn2  = (const float*)d_in[13];
    const float* bn3  = (const float*)d_in[14];
    const float* dW   = (const float*)d_in[15];
    const float* db   = (const float*)d_in[16];
    const float* hW   = (const float*)d_in[17];
    const float* hb   = (const float*)d_in[18];

    float *rel, *bufA, *bufB, *h, *ssum;
    unsigned* smax;
    cudaGetSymbolAddress((void**)&rel,  g_rel);
    cudaGetSymbolAddress((void**)&bufA, g_bufA);
    cudaGetSymbolAddress((void**)&bufB, g_bufB);
    cudaGetSymbolAddress((void**)&h,    g_h);
    cudaGetSymbolAddress((void**)&ssum, g_sum);
    cudaGetSymbolAddress((void**)&smax, g_maxu);

    float* out        = (float*)d_out;
    float* out_soft   = out;
    float* out_logits = out + 1024 * 24;
    float* out_fp     = out + 2 * 1024 * 24;

    // ---------------- layer 1 (K = 75) ----------------
    for (int d = 1; d <= 4; d++) {
        int n = SEG_SIZE[d], tot = n * 75;
        gather_sum<<<(tot + 255) / 256, 256>>>(atom, 75, adj[d - 1], d, n,
                                               rel + (long)REL_OFF[d] * 75);
    }
    conv_gemm_mma<<<dim3(2, 512), 256>>>(atom, 75, 3, rel, gc1W, gc1b, bn1, bufA);
    cudaMemcpyAsync(bufB, bufA, (size_t)4096 * 256 * sizeof(float),
                    cudaMemcpyDeviceToDevice);
    for (int d = 1; d <= 4; d++) {
        int n = SEG_SIZE[d], tot = n * 256;
        pool_max<<<(tot + 255) / 256, 256>>>(bufA, adj[d - 1], d, n, SEG_START[d], bufB);
    }

    // ---------------- layer 2 (K = 256) ----------------
    for (int d = 1; d <= 4; d++) {
        int n = SEG_SIZE[d], tot = n * 256;
        gather_sum<<<(tot + 255) / 256, 256>>>(bufB, 256, adj[d - 1], d, n,
                                               rel + (long)REL_OFF[d] * 256);
    }
    conv_gemm_mma<<<dim3(2, 512), 256>>>(bufB, 256, 8, rel, gc2W, gc2b, bn2, bufA);
    cudaMemcpyAsync(bufB, bufA, (size_t)4096 * 256 * sizeof(float),
                    cudaMemcpyDeviceToDevice);
    for (int d = 1; d <= 4; d++) {
        int n = SEG_SIZE[d], tot = n * 256;
        pool_max<<<(tot + 255) / 256, 256>>>(bufA, adj[d - 1], d, n, SEG_START[d], bufB);
    }

    // ---------------- dense + BN3 ----------------
    dense_gemm_mma<<<dim3(4, 512), 256>>>(bufB, dW, db, bn3, h);

    // ---------------- segment sum/max ----------------
    seg_init<<<(1024 * 512 + 255) / 256, 256>>>(ssum, smax);
    seg_reduce<<<(65536 * 512 + 255) / 256, 256>>>(h, membership, ssum, smax);

    // ---------------- fp / head / softmax ----------------
    fp_tanh<<<(1024 * 1024 + 255) / 256, 256>>>(ssum, smax, out_fp);
    head_kernel<<<1024, 256>>>(out_fp, hW, hb, out_soft, out_logits);
}